// round 13
// baseline (speedup 1.0000x reference)
#include <cuda_runtime.h>

#define G 128
#define H 64
#define Q 32

// ---------------- constant weights (warp-uniform access only) ---------------
__constant__ unsigned long long cW1u[216];   // W1 (27,16) as ch-pair f32x2
__constant__ unsigned long long cW2t[864];   // W2 repacked [tap][co][ci-pair]
__constant__ float cWt1[2*2*2*4*16];         // (2,2,2,4,16)
__constant__ float cWt2[2*2*2*16];           // (2,2,2,16,1)

// ---------------- scratch (device globals; no allocs allowed) ---------------
__device__ float g_hp1[2u*64*64*64*16]; // pooled stage-1 activations, NDHWC
__device__ float g_hp2[2u*32*32*32*4];  // pooled stage-2 activations, NDHWC
__device__ unsigned char g_m1[2u*64*64*64];
__device__ unsigned char g_m2[2u*32*32*32];
__device__ unsigned long long g_w2t[864];   // staging for cW2t

__device__ __forceinline__ float frelu(float v) { return v > 0.f ? v : 0.f; }
__device__ __forceinline__ float fsig(float v) { return 1.f / (1.f + __expf(-v)); }

// packed fp32x2 helpers (Blackwell FFMA2 — only reachable via PTX)
__device__ __forceinline__ unsigned long long dup2(float a) {
    unsigned long long r;
    asm("mov.b64 %0, {%1, %1};" : "=l"(r) : "f"(a));
    return r;
}
__device__ __forceinline__ void fma2(unsigned long long& d,
                                     unsigned long long a, unsigned long long b) {
    asm("fma.rn.f32x2 %0, %1, %2, %0;" : "+l"(d) : "l"(a), "l"(b));
}
__device__ __forceinline__ float lo32(unsigned long long v) {
    return __uint_as_float((unsigned)v);
}
__device__ __forceinline__ float hi32(unsigned long long v) {
    return __uint_as_float((unsigned)(v >> 32));
}

// ============================================================================
// K0: repack W2 (27,16,4) -> [tap][co][ci-pair] packed f32x2 (864 entries)
// ============================================================================
__global__ void k0_repack(const float* __restrict__ W2)
{
    int i = blockIdx.x*256 + threadIdx.x;
    if (i < 864) {
        int tap = i >> 5, r = i & 31, co = r >> 3, p = r & 7;
        unsigned lo = __float_as_uint(W2[tap*64 + (2*p  )*4 + co]);
        unsigned hi = __float_as_uint(W2[tap*64 + (2*p+1)*4 + co]);
        g_w2t[i] = (unsigned long long)lo | ((unsigned long long)hi << 32);
    }
}

// ============================================================================
// K1: xm = x*(occ==0); h1 = relu(conv3(xm,W1))*m0; hp1 = maxpool2(h1)
// Compacted active list -> VOXEL-PER-THREAD (2 voxels/thread): all 16 output
// channels in 8 FFMA2 accumulators; weights via warp-uniform LDCU (ch-pairs
// are contiguous in W1's (tap,ch) layout). Only ~1 warp/block runs the conv.
// ============================================================================
__global__ __launch_bounds__(256) void k1_conv1_pool(const float* __restrict__ x,
                                                     const int* __restrict__ occ)
{
    __shared__ float xs[1000];              // 10^3 masked-x halo
    __shared__ unsigned short lst[512];     // compacted active fine voxels
    __shared__ int cnt;
    __shared__ int cellact[64];             // any-active per pooled cell
    __shared__ float pl[1024];              // pooled accum [cell][ch]

    int bi  = blockIdx.x;
    int b   = bi >> 12;
    int tz  = (bi >> 8) & 15, ty = (bi >> 4) & 15, tx = bi & 15;
    int tid = threadIdx.x;

    if (tid == 0) cnt = 0;
    if (tid < 64) cellact[tid] = 0;
    #pragma unroll
    for (int it = 0; it < 4; it++) pl[tid + it*256] = 0.f;
    __syncthreads();

    int fz0 = tz*8, fy0 = ty*8, fx0 = tx*8;
    int baseb = b * (G*G*G);

    #pragma unroll
    for (int it = 0; it < 4; it++) {
        int i = tid + it*256;
        if (i < 1000) {
            int z = i/100, y = (i/10)%10, xx = i%10;
            int gz = fz0+z-1, gy = fy0+y-1, gx = fx0+xx-1;
            float v = 0.f;
            int   o = 1;
            bool inb = ((unsigned)gz < G) & ((unsigned)gy < G) & ((unsigned)gx < G);
            if (inb) {
                int idx = baseb + (gz*G + gy)*G + gx;
                o = occ[idx];
                v = x[idx];
            }
            bool act = inb && (o == 0);
            xs[i] = act ? v : 0.f;
            if (act && z >= 1 && z <= 8 && y >= 1 && y <= 8 && xx >= 1 && xx <= 8) {
                int lz = z-1, ly = y-1, lx = xx-1;
                int p = atomicAdd(&cnt, 1);
                lst[p] = (unsigned short)((lz<<6) | (ly<<3) | lx);
                atomicOr(&cellact[((lz>>1)<<4) | ((ly>>1)<<2) | (lx>>1)], 1);
            }
        }
    }
    __syncthreads();

    int n = cnt;
    int t0 = tid*2;
    if (t0 < n) {
        bool has1 = (t0 + 1 < n);
        int c0 = lst[t0];
        int c1 = lst[has1 ? t0+1 : t0];
        int lz0 = c0 >> 6, ly0 = (c0 >> 3) & 7, lx0 = c0 & 7;
        int lz1 = c1 >> 6, ly1 = (c1 >> 3) & 7, lx1 = c1 & 7;
        const float* xp0 = &xs[lz0*100 + ly0*10 + lx0];
        const float* xp1 = &xs[lz1*100 + ly1*10 + lx1];

        unsigned long long A[8], Bv[8];
        #pragma unroll
        for (int c = 0; c < 8; c++) { A[c] = 0ull; Bv[c] = 0ull; }

        #pragma unroll
        for (int dz = 0; dz < 3; dz++)
        #pragma unroll
        for (int dy = 0; dy < 3; dy++)
        #pragma unroll
        for (int dx = 0; dx < 3; dx++) {
            int off = dz*100 + dy*10 + dx;
            int tap = (dz*3 + dy)*3 + dx;
            unsigned long long d0 = dup2(xp0[off]);
            unsigned long long d1 = dup2(xp1[off]);
            #pragma unroll
            for (int c = 0; c < 8; c++) {
                unsigned long long w = cW1u[tap*8 + c];   // warp-uniform LDCU
                fma2(A[c],  d0, w);
                fma2(Bv[c], d1, w);
            }
        }

        int cell0 = ((lz0>>1)<<4) | ((ly0>>1)<<2) | (lx0>>1);
        int cell1 = ((lz1>>1)<<4) | ((ly1>>1)<<2) | (lx1>>1);
        #pragma unroll
        for (int c = 0; c < 8; c++) {
            atomicMax((int*)&pl[cell0*16 + 2*c    ], __float_as_int(frelu(lo32(A[c]))));
            atomicMax((int*)&pl[cell0*16 + 2*c + 1], __float_as_int(frelu(hi32(A[c]))));
            if (has1) {
                atomicMax((int*)&pl[cell1*16 + 2*c    ], __float_as_int(frelu(lo32(Bv[c]))));
                atomicMax((int*)&pl[cell1*16 + 2*c + 1], __float_as_int(frelu(hi32(Bv[c]))));
            }
        }
    }
    __syncthreads();

    #pragma unroll
    for (int it = 0; it < 4; it++) {
        int i = tid + it*256;
        int cell = i >> 4, c2 = i & 15;
        int cz = cell >> 4, cy = (cell >> 2) & 3, cx = cell & 3;
        int pz = tz*4 + cz, py = ty*4 + cy, px = tx*4 + cx;
        int pidx = ((b*H + pz)*H + py)*H + px;
        g_hp1[(pidx << 4) + c2] = pl[i];
        if (c2 == 0) g_m1[pidx] = (unsigned char)(cellact[cell] != 0);
    }
}

// ============================================================================
// K2: h2 = relu(conv3(hp1,W2))*m1; hp2 = maxpool2(h2); emits m2.
// Compacted list, 2 VOXELS/THREAD. FFMA2 paired over ci (adjacent in ts ->
// aligned LDS.64, NO dup movs); weights cW2t [tap][co][ci-pair] via uniform
// LDCU, amortized across both voxels. XOR-swizzled ts quads (R9, proven).
// ============================================================================
__global__ __launch_bounds__(512) void k2_conv2_pool()
{
    extern __shared__ float ts[];            // 10*10*10*16 floats = 64000 B
    __shared__ float hs[512*4];              // per-voxel relu'd masked outputs
    __shared__ unsigned char sm1[512];       // per-voxel m1
    __shared__ unsigned short lst[512];      // compacted active voxels
    __shared__ int cnt;

    int bi  = blockIdx.x;
    int b   = bi >> 9;
    int t   = bi & 511;
    int tz  = t >> 6, ty = (t >> 3) & 7, tx = t & 7;
    int tid = threadIdx.x;

    if (tid == 0) cnt = 0;
    *(float4*)&hs[tid*4] = make_float4(0.f, 0.f, 0.f, 0.f);

    int fz0 = tz*8, fy0 = ty*8, fx0 = tx*8;

    // halo load with per-voxel XOR slot swizzle: data quad q -> slot q^(i&3)
    for (int i = tid; i < 1000; i += 512) {
        int z = i/100, y = (i/10)%10, xx = i%10;
        int gz = fz0+z-1, gy = fy0+y-1, gx = fx0+xx-1;
        float4* dst = (float4*)&ts[i*16];
        int s = i & 3;
        if ((unsigned)gz < H && (unsigned)gy < H && (unsigned)gx < H) {
            const float4* src = (const float4*)&g_hp1[(((b*H+gz)*H + gy)*H + gx)*16];
            dst[0^s] = src[0]; dst[1^s] = src[1]; dst[2^s] = src[2]; dst[3^s] = src[3];
        } else {
            float4 zz = make_float4(0.f, 0.f, 0.f, 0.f);
            dst[0] = zz; dst[1] = zz; dst[2] = zz; dst[3] = zz;
        }
    }

    // m1 + compaction
    {
        int lz = tid >> 6, ly = (tid >> 3) & 7, lx = tid & 7;
        int uz = fz0 + lz, uy = fy0 + ly, ux = fx0 + lx;
        unsigned char m1 = g_m1[((b*H + uz)*H + uy)*H + ux];
        sm1[tid] = m1;
        if (m1) {
            int p = atomicAdd(&cnt, 1);
            lst[p] = (unsigned short)tid;
        }
    }
    __syncthreads();

    int n = cnt;
    int t0 = tid*2;
    if (t0 < n) {
        bool has1 = (t0 + 1 < n);
        int code0 = lst[t0];
        int code1 = lst[has1 ? t0+1 : t0];
        int lz0 = code0 >> 6, ly0 = (code0 >> 3) & 7, lx0 = code0 & 7;
        int lz1 = code1 >> 6, ly1 = (code1 >> 3) & 7, lx1 = code1 & 7;

        unsigned long long a0[4], a1[4];   // per-co (even-ci, odd-ci) partials
        #pragma unroll
        for (int c = 0; c < 4; c++) { a0[c] = 0ull; a1[c] = 0ull; }

        #pragma unroll 1
        for (int dz = 0; dz < 3; dz++) {
            #pragma unroll 1
            for (int dy = 0; dy < 3; dy++) {
                int rb0 = (lz0+dz)*100 + (ly0+dy)*10 + lx0;
                int rb1 = (lz1+dz)*100 + (ly1+dy)*10 + lx1;
                int wb  = ((dz*3 + dy)*3) * 32;
                #pragma unroll
                for (int dx = 0; dx < 3; dx++) {
                    int row0 = rb0 + dx, row1 = rb1 + dx;
                    int s0 = row0 & 3,  s1 = row1 & 3;
                    const float* p0 = &ts[row0*16];
                    const float* p1 = &ts[row1*16];
                    unsigned long long x0[8], x1[8];
                    #pragma unroll
                    for (int p = 0; p < 8; p++) {
                        x0[p] = *(const unsigned long long*)
                                 (p0 + (((p>>1)^s0)<<2) + ((p&1)<<1));
                        x1[p] = *(const unsigned long long*)
                                 (p1 + (((p>>1)^s1)<<2) + ((p&1)<<1));
                    }
                    #pragma unroll
                    for (int co = 0; co < 4; co++)
                    #pragma unroll
                    for (int p = 0; p < 8; p++) {
                        unsigned long long w = cW2t[wb + dx*32 + co*8 + p]; // uniform LDCU
                        fma2(a0[co], x0[p], w);
                        fma2(a1[co], x1[p], w);
                    }
                }
            }
        }
        {
            float o0 = frelu(lo32(a0[0]) + hi32(a0[0]));
            float o1 = frelu(lo32(a0[1]) + hi32(a0[1]));
            float o2 = frelu(lo32(a0[2]) + hi32(a0[2]));
            float o3 = frelu(lo32(a0[3]) + hi32(a0[3]));
            *(float4*)&hs[code0*4] = make_float4(o0, o1, o2, o3);
        }
        if (has1) {
            float o0 = frelu(lo32(a1[0]) + hi32(a1[0]));
            float o1 = frelu(lo32(a1[1]) + hi32(a1[1]));
            float o2 = frelu(lo32(a1[2]) + hi32(a1[2]));
            float o3 = frelu(lo32(a1[3]) + hi32(a1[3]));
            *(float4*)&hs[code1*4] = make_float4(o0, o1, o2, o3);
        }
    }
    __syncthreads();

    // pool 2x2x2 + m2
    if (tid < 256) {
        int cell = tid >> 2, co = tid & 3;
        int cz = cell >> 4, cy = (cell >> 2) & 3, cx = cell & 3;
        float mv = 0.f;
        int anym = 0;
        #pragma unroll
        for (int k = 0; k < 8; k++) {
            int child = (((cz*2 + ((k>>2)&1)) << 6) |
                         ((cy*2 + ((k>>1)&1)) << 3) |
                          (cx*2 + (k&1)));
            mv = fmaxf(mv, hs[child*4 + co]);
            anym |= sm1[child];
        }
        int pz = tz*4 + cz, py = ty*4 + cy, px = tx*4 + cx;
        int cidx = ((b*Q + pz)*Q + py)*Q + px;
        g_hp2[cidx*4 + co] = mv;
        if (co == 0) g_m2[cidx] = (unsigned char)(anym != 0);
    }
}

// ============================================================================
// K3: fused decoder; m2 from g_m2 (no occ traffic). Direct float4 stores.
//   h3(2i+d,co) = relu(sum_ci hp2(i,ci)*Wt1[1-d][ci][co])   (conv_transpose flip)
//   out(2u+e)   = sigmoid(sum_co h3(u,co)*Wt2[1-e][co]) * m
// ============================================================================
__global__ __launch_bounds__(256) void k3_tconv(float* __restrict__ out)
{
    int gid = blockIdx.x*256 + threadIdx.x;
    int b  = gid >> 15;
    int c  = gid & 32767;
    int iz = c >> 10, iy = (c >> 5) & 31, ix = c & 31;

    int obase = ((b*G + 4*iz)*G + 4*iy)*G + 4*ix;

    if (!g_m2[gid]) {
        float4 zz = make_float4(0.f, 0.f, 0.f, 0.f);
        #pragma unroll
        for (int r = 0; r < 16; r++) {
            int wz = r >> 2, wy = r & 3;
            *(float4*)&out[obase + (wz*G + wy)*G] = zz;
        }
        return;
    }

    const float4 hin = *(const float4*)&g_hp2[gid*4];

    #pragma unroll
    for (int dz = 0; dz < 2; dz++)
    #pragma unroll
    for (int dy = 0; dy < 2; dy++) {
        float h3a[16], h3b[16];
        {
            const float* wA = &cWt1[(((1-dz)*2 + (1-dy))*2 + 1)*64]; // dx=0
            const float* wB = &cWt1[(((1-dz)*2 + (1-dy))*2 + 0)*64]; // dx=1
            #pragma unroll
            for (int co = 0; co < 16; co++) {
                float va = fmaf(hin.x, wA[co],
                           fmaf(hin.y, wA[16+co],
                           fmaf(hin.z, wA[32+co], hin.w * wA[48+co])));
                float vb = fmaf(hin.x, wB[co],
                           fmaf(hin.y, wB[16+co],
                           fmaf(hin.z, wB[32+co], hin.w * wB[48+co])));
                h3a[co] = frelu(va);
                h3b[co] = frelu(vb);
            }
        }
        #pragma unroll
        for (int ez = 0; ez < 2; ez++)
        #pragma unroll
        for (int ey = 0; ey < 2; ey++) {
            const float* w2e0 = &cWt2[((((1-ez)*2 + (1-ey))*2) + 1)*16]; // ex=0
            const float* w2e1 = &cWt2[((((1-ez)*2 + (1-ey))*2) + 0)*16]; // ex=1
            float sx = 0.f, sy = 0.f, sz = 0.f, sw = 0.f;
            #pragma unroll
            for (int co = 0; co < 16; co++) {
                sx = fmaf(h3a[co], w2e0[co], sx);
                sy = fmaf(h3a[co], w2e1[co], sy);
                sz = fmaf(h3b[co], w2e0[co], sz);
                sw = fmaf(h3b[co], w2e1[co], sw);
            }
            float4 o = make_float4(fsig(sx), fsig(sy), fsig(sz), fsig(sw));
            int wz = 2*dz + ez, wy = 2*dy + ey;
            *(float4*)&out[obase + (wz*G + wy)*G] = o;
        }
    }
}

// ============================================================================
extern "C" void kernel_launch(void* const* d_in, const int* in_sizes, int n_in,
                              void* d_out, int out_size)
{
    const float* x   = (const float*)d_in[0];
    const float* W1  = (const float*)d_in[1];
    const float* W2  = (const float*)d_in[2];
    const float* Wt1 = (const float*)d_in[3];
    const float* Wt2 = (const float*)d_in[4];
    const int*   occ = (const int*)  d_in[5];

    int B = in_sizes[0] / (G*G*G);

    // W1 channel-pairs are already contiguous: raw copy into cW1u
    cudaMemcpyToSymbolAsync(cW1u, W1,  3*3*3*16*sizeof(float),   0, cudaMemcpyDeviceToDevice, 0);
    cudaMemcpyToSymbolAsync(cWt1, Wt1, 2*2*2*4*16*sizeof(float), 0, cudaMemcpyDeviceToDevice, 0);
    cudaMemcpyToSymbolAsync(cWt2, Wt2, 2*2*2*16*sizeof(float),   0, cudaMemcpyDeviceToDevice, 0);

    // repack W2 on device, then stage into constant memory (D2D, capturable)
    k0_repack<<<4, 256>>>(W2);
    void* w2t_addr = nullptr;
    cudaGetSymbolAddress(&w2t_addr, g_w2t);
    cudaMemcpyToSymbolAsync(cW2t, w2t_addr, 864*sizeof(unsigned long long),
                            0, cudaMemcpyDeviceToDevice, 0);

    cudaFuncSetAttribute(k2_conv2_pool, cudaFuncAttributeMaxDynamicSharedMemorySize, 64000);

    k1_conv1_pool<<<B*4096, 256>>>(x, occ);
    k2_conv2_pool<<<B*512, 512, 64000>>>();
    k3_tconv<<<B*128, 256>>>((float*)d_out);
}

// round 14
// speedup vs baseline: 1.0258x; 1.0258x over previous
#include <cuda_runtime.h>

#define G 128
#define H 64
#define Q 32

// ---------------- constant weights (warp-uniform access only) ---------------
__constant__ unsigned long long cW2t[864];   // W2 repacked [tap][co][ci-pair]
__constant__ float cWt1[2*2*2*4*16];         // (2,2,2,4,16)
__constant__ float cWt2[2*2*2*16];           // (2,2,2,16,1)

// ---------------- scratch (device globals; no allocs allowed) ---------------
__device__ float g_hp1[2u*64*64*64*16]; // pooled stage-1 activations, NDHWC
__device__ float g_hp2[2u*32*32*32*4];  // pooled stage-2 activations, NDHWC
__device__ unsigned char g_m1[2u*64*64*64];
__device__ unsigned char g_m2[2u*32*32*32];
__device__ unsigned long long g_w2t[864];   // staging for cW2t

__device__ __forceinline__ float frelu(float v) { return v > 0.f ? v : 0.f; }
__device__ __forceinline__ float fsig(float v) { return 1.f / (1.f + __expf(-v)); }

// packed fp32x2 helpers (Blackwell FFMA2 — only reachable via PTX)
__device__ __forceinline__ void fma2(unsigned long long& d,
                                     unsigned long long a, unsigned long long b) {
    asm("fma.rn.f32x2 %0, %1, %2, %0;" : "+l"(d) : "l"(a), "l"(b));
}
__device__ __forceinline__ float lo32(unsigned long long v) {
    return __uint_as_float((unsigned)v);
}
__device__ __forceinline__ float hi32(unsigned long long v) {
    return __uint_as_float((unsigned)(v >> 32));
}

// ============================================================================
// K0: repack W2 (27,16,4) -> [tap][co][ci-pair] packed f32x2 (864 entries)
// ============================================================================
__global__ void k0_repack(const float* __restrict__ W2)
{
    int i = blockIdx.x*256 + threadIdx.x;
    if (i < 864) {
        int tap = i >> 5, r = i & 31, co = r >> 3, p = r & 7;
        unsigned lo = __float_as_uint(W2[tap*64 + (2*p  )*4 + co]);
        unsigned hi = __float_as_uint(W2[tap*64 + (2*p+1)*4 + co]);
        g_w2t[i] = (unsigned long long)lo | ((unsigned long long)hi << 32);
    }
}

// ============================================================================
// K1 (R9 proven version, 57.6us): xm = x*(occ==0); h1 = relu(conv3(xm,W1))*m0;
// hp1 = maxpool2(h1). Compacted active list -> dense passes with 16 threads
// (= channels) per voxel; weights in registers (27/thread). Emits m1 bytes.
// Work and atomics spread across all 8 warps.
// ============================================================================
__global__ __launch_bounds__(256) void k1_conv1_pool(const float* __restrict__ x,
                                                     const int* __restrict__ occ,
                                                     const float* __restrict__ W1)
{
    __shared__ float xs[1000];              // 10^3 masked-x halo
    __shared__ unsigned short lst[512];     // compacted active fine voxels
    __shared__ int cnt;
    __shared__ int cellact[64];             // any-active per pooled cell
    __shared__ float pl[1024];              // pooled accum [cell][ch]

    int bi  = blockIdx.x;
    int b   = bi >> 12;
    int tz  = (bi >> 8) & 15, ty = (bi >> 4) & 15, tx = bi & 15;
    int tid = threadIdx.x;
    int ch  = tid & 15;
    int g   = tid >> 4;

    float w[27];
    #pragma unroll
    for (int t = 0; t < 27; t++) w[t] = W1[t*16 + ch];

    if (tid == 0) cnt = 0;
    if (tid < 64) cellact[tid] = 0;
    #pragma unroll
    for (int it = 0; it < 4; it++) pl[tid + it*256] = 0.f;
    __syncthreads();

    int fz0 = tz*8, fy0 = ty*8, fx0 = tx*8;
    int baseb = b * (G*G*G);

    #pragma unroll
    for (int it = 0; it < 4; it++) {
        int i = tid + it*256;
        if (i < 1000) {
            int z = i/100, y = (i/10)%10, xx = i%10;
            int gz = fz0+z-1, gy = fy0+y-1, gx = fx0+xx-1;
            float v = 0.f;
            int   o = 1;
            bool inb = ((unsigned)gz < G) & ((unsigned)gy < G) & ((unsigned)gx < G);
            if (inb) {
                int idx = baseb + (gz*G + gy)*G + gx;
                o = occ[idx];
                v = x[idx];
            }
            bool act = inb && (o == 0);
            xs[i] = act ? v : 0.f;
            if (act && z >= 1 && z <= 8 && y >= 1 && y <= 8 && xx >= 1 && xx <= 8) {
                int lz = z-1, ly = y-1, lx = xx-1;
                int p = atomicAdd(&cnt, 1);
                lst[p] = (unsigned short)((lz<<6) | (ly<<3) | lx);
                atomicOr(&cellact[((lz>>1)<<4) | ((ly>>1)<<2) | (lx>>1)], 1);
            }
        }
    }
    __syncthreads();

    int n = cnt;
    for (int base = 0; base < n; base += 16) {
        int vi = base + g;
        if (vi < n) {
            int code = lst[vi];
            int lz = code >> 6, ly = (code >> 3) & 7, lx = code & 7;
            const float* xp = &xs[lz*100 + ly*10 + lx];
            float acc = 0.f;
            #pragma unroll
            for (int dz = 0; dz < 3; dz++)
            #pragma unroll
            for (int dy = 0; dy < 3; dy++)
            #pragma unroll
            for (int dx = 0; dx < 3; dx++)
                acc = fmaf(xp[dz*100 + dy*10 + dx], w[(dz*3+dy)*3+dx], acc);
            acc = frelu(acc);
            int cell = ((lz>>1)<<4) | ((ly>>1)<<2) | (lx>>1);
            atomicMax((int*)&pl[cell*16 + ch], __float_as_int(acc)); // nonneg floats
        }
    }
    __syncthreads();

    #pragma unroll
    for (int it = 0; it < 4; it++) {
        int i = tid + it*256;
        int cell = i >> 4, c2 = i & 15;
        int cz = cell >> 4, cy = (cell >> 2) & 3, cx = cell & 3;
        int pz = tz*4 + cz, py = ty*4 + cy, px = tx*4 + cx;
        int pidx = ((b*H + pz)*H + py)*H + px;
        g_hp1[(pidx << 4) + c2] = pl[i];
        if (c2 == 0) g_m1[pidx] = (unsigned char)(cellact[cell] != 0);
    }
}

// ============================================================================
// K2 (R13 version under test): h2 = relu(conv3(hp1,W2))*m1; hp2 = maxpool2(h2).
// Compacted list, 2 voxels/thread. FFMA2 paired over ci (aligned LDS.64, no
// dup movs); weights cW2t via warp-uniform LDCU amortized across both voxels.
// XOR-swizzled ts quads. Emits m2.
// ============================================================================
__global__ __launch_bounds__(512) void k2_conv2_pool()
{
    extern __shared__ float ts[];            // 10*10*10*16 floats = 64000 B
    __shared__ float hs[512*4];              // per-voxel relu'd masked outputs
    __shared__ unsigned char sm1[512];       // per-voxel m1
    __shared__ unsigned short lst[512];      // compacted active voxels
    __shared__ int cnt;

    int bi  = blockIdx.x;
    int b   = bi >> 9;
    int t   = bi & 511;
    int tz  = t >> 6, ty = (t >> 3) & 7, tx = t & 7;
    int tid = threadIdx.x;

    if (tid == 0) cnt = 0;
    *(float4*)&hs[tid*4] = make_float4(0.f, 0.f, 0.f, 0.f);

    int fz0 = tz*8, fy0 = ty*8, fx0 = tx*8;

    // halo load with per-voxel XOR slot swizzle: data quad q -> slot q^(i&3)
    for (int i = tid; i < 1000; i += 512) {
        int z = i/100, y = (i/10)%10, xx = i%10;
        int gz = fz0+z-1, gy = fy0+y-1, gx = fx0+xx-1;
        float4* dst = (float4*)&ts[i*16];
        int s = i & 3;
        if ((unsigned)gz < H && (unsigned)gy < H && (unsigned)gx < H) {
            const float4* src = (const float4*)&g_hp1[(((b*H+gz)*H + gy)*H + gx)*16];
            dst[0^s] = src[0]; dst[1^s] = src[1]; dst[2^s] = src[2]; dst[3^s] = src[3];
        } else {
            float4 zz = make_float4(0.f, 0.f, 0.f, 0.f);
            dst[0] = zz; dst[1] = zz; dst[2] = zz; dst[3] = zz;
        }
    }

    // m1 + compaction
    {
        int lz = tid >> 6, ly = (tid >> 3) & 7, lx = tid & 7;
        int uz = fz0 + lz, uy = fy0 + ly, ux = fx0 + lx;
        unsigned char m1 = g_m1[((b*H + uz)*H + uy)*H + ux];
        sm1[tid] = m1;
        if (m1) {
            int p = atomicAdd(&cnt, 1);
            lst[p] = (unsigned short)tid;
        }
    }
    __syncthreads();

    int n = cnt;
    int t0 = tid*2;
    if (t0 < n) {
        bool has1 = (t0 + 1 < n);
        int code0 = lst[t0];
        int code1 = lst[has1 ? t0+1 : t0];
        int lz0 = code0 >> 6, ly0 = (code0 >> 3) & 7, lx0 = code0 & 7;
        int lz1 = code1 >> 6, ly1 = (code1 >> 3) & 7, lx1 = code1 & 7;

        unsigned long long a0[4], a1[4];   // per-co (even-ci, odd-ci) partials
        #pragma unroll
        for (int c = 0; c < 4; c++) { a0[c] = 0ull; a1[c] = 0ull; }

        #pragma unroll 1
        for (int dz = 0; dz < 3; dz++) {
            #pragma unroll 1
            for (int dy = 0; dy < 3; dy++) {
                int rb0 = (lz0+dz)*100 + (ly0+dy)*10 + lx0;
                int rb1 = (lz1+dz)*100 + (ly1+dy)*10 + lx1;
                int wb  = ((dz*3 + dy)*3) * 32;
                #pragma unroll
                for (int dx = 0; dx < 3; dx++) {
                    int row0 = rb0 + dx, row1 = rb1 + dx;
                    int s0 = row0 & 3,  s1 = row1 & 3;
                    const float* p0 = &ts[row0*16];
                    const float* p1 = &ts[row1*16];
                    unsigned long long x0[8], x1[8];
                    #pragma unroll
                    for (int p = 0; p < 8; p++) {
                        x0[p] = *(const unsigned long long*)
                                 (p0 + (((p>>1)^s0)<<2) + ((p&1)<<1));
                        x1[p] = *(const unsigned long long*)
                                 (p1 + (((p>>1)^s1)<<2) + ((p&1)<<1));
                    }
                    #pragma unroll
                    for (int co = 0; co < 4; co++)
                    #pragma unroll
                    for (int p = 0; p < 8; p++) {
                        unsigned long long w = cW2t[wb + dx*32 + co*8 + p]; // uniform LDCU
                        fma2(a0[co], x0[p], w);
                        fma2(a1[co], x1[p], w);
                    }
                }
            }
        }
        {
            float o0 = frelu(lo32(a0[0]) + hi32(a0[0]));
            float o1 = frelu(lo32(a0[1]) + hi32(a0[1]));
            float o2 = frelu(lo32(a0[2]) + hi32(a0[2]));
            float o3 = frelu(lo32(a0[3]) + hi32(a0[3]));
            *(float4*)&hs[code0*4] = make_float4(o0, o1, o2, o3);
        }
        if (has1) {
            float o0 = frelu(lo32(a1[0]) + hi32(a1[0]));
            float o1 = frelu(lo32(a1[1]) + hi32(a1[1]));
            float o2 = frelu(lo32(a1[2]) + hi32(a1[2]));
            float o3 = frelu(lo32(a1[3]) + hi32(a1[3]));
            *(float4*)&hs[code1*4] = make_float4(o0, o1, o2, o3);
        }
    }
    __syncthreads();

    // pool 2x2x2 + m2
    if (tid < 256) {
        int cell = tid >> 2, co = tid & 3;
        int cz = cell >> 4, cy = (cell >> 2) & 3, cx = cell & 3;
        float mv = 0.f;
        int anym = 0;
        #pragma unroll
        for (int k = 0; k < 8; k++) {
            int child = (((cz*2 + ((k>>2)&1)) << 6) |
                         ((cy*2 + ((k>>1)&1)) << 3) |
                          (cx*2 + (k&1)));
            mv = fmaxf(mv, hs[child*4 + co]);
            anym |= sm1[child];
        }
        int pz = tz*4 + cz, py = ty*4 + cy, px = tx*4 + cx;
        int cidx = ((b*Q + pz)*Q + py)*Q + px;
        g_hp2[cidx*4 + co] = mv;
        if (co == 0) g_m2[cidx] = (unsigned char)(anym != 0);
    }
}

// ============================================================================
// K3: fused decoder; m2 from g_m2 (no occ traffic). Direct float4 stores.
//   h3(2i+d,co) = relu(sum_ci hp2(i,ci)*Wt1[1-d][ci][co])   (conv_transpose flip)
//   out(2u+e)   = sigmoid(sum_co h3(u,co)*Wt2[1-e][co]) * m
// ============================================================================
__global__ __launch_bounds__(256) void k3_tconv(float* __restrict__ out)
{
    int gid = blockIdx.x*256 + threadIdx.x;
    int b  = gid >> 15;
    int c  = gid & 32767;
    int iz = c >> 10, iy = (c >> 5) & 31, ix = c & 31;

    int obase = ((b*G + 4*iz)*G + 4*iy)*G + 4*ix;

    if (!g_m2[gid]) {
        float4 zz = make_float4(0.f, 0.f, 0.f, 0.f);
        #pragma unroll
        for (int r = 0; r < 16; r++) {
            int wz = r >> 2, wy = r & 3;
            *(float4*)&out[obase + (wz*G + wy)*G] = zz;
        }
        return;
    }

    const float4 hin = *(const float4*)&g_hp2[gid*4];

    #pragma unroll
    for (int dz = 0; dz < 2; dz++)
    #pragma unroll
    for (int dy = 0; dy < 2; dy++) {
        float h3a[16], h3b[16];
        {
            const float* wA = &cWt1[(((1-dz)*2 + (1-dy))*2 + 1)*64]; // dx=0
            const float* wB = &cWt1[(((1-dz)*2 + (1-dy))*2 + 0)*64]; // dx=1
            #pragma unroll
            for (int co = 0; co < 16; co++) {
                float va = fmaf(hin.x, wA[co],
                           fmaf(hin.y, wA[16+co],
                           fmaf(hin.z, wA[32+co], hin.w * wA[48+co])));
                float vb = fmaf(hin.x, wB[co],
                           fmaf(hin.y, wB[16+co],
                           fmaf(hin.z, wB[32+co], hin.w * wB[48+co])));
                h3a[co] = frelu(va);
                h3b[co] = frelu(vb);
            }
        }
        #pragma unroll
        for (int ez = 0; ez < 2; ez++)
        #pragma unroll
        for (int ey = 0; ey < 2; ey++) {
            const float* w2e0 = &cWt2[((((1-ez)*2 + (1-ey))*2) + 1)*16]; // ex=0
            const float* w2e1 = &cWt2[((((1-ez)*2 + (1-ey))*2) + 0)*16]; // ex=1
            float sx = 0.f, sy = 0.f, sz = 0.f, sw = 0.f;
            #pragma unroll
            for (int co = 0; co < 16; co++) {
                sx = fmaf(h3a[co], w2e0[co], sx);
                sy = fmaf(h3a[co], w2e1[co], sy);
                sz = fmaf(h3b[co], w2e0[co], sz);
                sw = fmaf(h3b[co], w2e1[co], sw);
            }
            float4 o = make_float4(fsig(sx), fsig(sy), fsig(sz), fsig(sw));
            int wz = 2*dz + ez, wy = 2*dy + ey;
            *(float4*)&out[obase + (wz*G + wy)*G] = o;
        }
    }
}

// ============================================================================
extern "C" void kernel_launch(void* const* d_in, const int* in_sizes, int n_in,
                              void* d_out, int out_size)
{
    const float* x   = (const float*)d_in[0];
    const float* W1  = (const float*)d_in[1];
    const float* W2  = (const float*)d_in[2];
    const float* Wt1 = (const float*)d_in[3];
    const float* Wt2 = (const float*)d_in[4];
    const int*   occ = (const int*)  d_in[5];

    int B = in_sizes[0] / (G*G*G);

    cudaMemcpyToSymbolAsync(cWt1, Wt1, 2*2*2*4*16*sizeof(float), 0, cudaMemcpyDeviceToDevice, 0);
    cudaMemcpyToSymbolAsync(cWt2, Wt2, 2*2*2*16*sizeof(float),   0, cudaMemcpyDeviceToDevice, 0);

    // repack W2 on device, then stage into constant memory (D2D, capturable)
    k0_repack<<<4, 256>>>(W2);
    void* w2t_addr = nullptr;
    cudaGetSymbolAddress(&w2t_addr, g_w2t);
    cudaMemcpyToSymbolAsync(cW2t, w2t_addr, 864*sizeof(unsigned long long),
                            0, cudaMemcpyDeviceToDevice, 0);

    cudaFuncSetAttribute(k2_conv2_pool, cudaFuncAttributeMaxDynamicSharedMemorySize, 64000);

    k1_conv1_pool<<<B*4096, 256>>>(x, occ, W1);
    k2_conv2_pool<<<B*512, 512, 64000>>>();
    k3_tconv<<<B*128, 256>>>((float*)d_out);
}